// round 15
// baseline (speedup 1.0000x reference)
#include <cuda_runtime.h>
#include <cuda_bf16.h>
#include <math.h>
#include <stdint.h>

// ---------------- scratch (no allocs allowed) ----------------
__device__ float g_qkv[8192 * 3072];                  // qkv projection fp32
__device__ __nv_bfloat16 g_xnh[8192 * 1024];          // layernormed x, split
__device__ __nv_bfloat16 g_xnl[8192 * 1024];
__device__ __nv_bfloat16 g_qh[8192 * 3072];           // split qkv (q,k rms-normed)
__device__ __nv_bfloat16 g_ql[8192 * 3072];
__device__ __nv_bfloat16 g_aoh[8192 * 1024];          // attention out, split
__device__ __nv_bfloat16 g_aol[8192 * 1024];
__device__ __nv_bfloat16 g_wth[3072 * 1024];          // w_qkv^T split [N][K]
__device__ __nv_bfloat16 g_wtl[3072 * 1024];
__device__ __nv_bfloat16 g_w2h[1024 * 1024];          // w_out^T split [N][K]
__device__ __nv_bfloat16 g_w2l[1024 * 1024];

#define DIMM 1024
#define DH 64

// ================= helpers =================
static __device__ __forceinline__ uint32_t s2u(const void* p) {
    uint32_t a;
    asm("{ .reg .u64 t; cvta.to.shared.u64 t, %1; cvt.u32.u64 %0, t; }" : "=r"(a) : "l"(p));
    return a;
}
static __device__ __forceinline__ void ldm4(uint32_t* r, uint32_t addr) {
    asm volatile("ldmatrix.sync.aligned.m8n8.x4.shared.b16 {%0,%1,%2,%3}, [%4];"
                 : "=r"(r[0]), "=r"(r[1]), "=r"(r[2]), "=r"(r[3]) : "r"(addr));
}
static __device__ __forceinline__ void ldm4t(uint32_t* r, uint32_t addr) {
    asm volatile("ldmatrix.sync.aligned.m8n8.x4.trans.shared.b16 {%0,%1,%2,%3}, [%4];"
                 : "=r"(r[0]), "=r"(r[1]), "=r"(r[2]), "=r"(r[3]) : "r"(addr));
}
static __device__ __forceinline__ void mma16816(float* c, const uint32_t* a, const uint32_t* b) {
    asm volatile(
        "mma.sync.aligned.m16n8k16.row.col.f32.bf16.bf16.f32 "
        "{%0,%1,%2,%3}, {%4,%5,%6,%7}, {%8,%9}, {%0,%1,%2,%3};"
        : "+f"(c[0]), "+f"(c[1]), "+f"(c[2]), "+f"(c[3])
        : "r"(a[0]), "r"(a[1]), "r"(a[2]), "r"(a[3]), "r"(b[0]), "r"(b[1]));
}
static __device__ __forceinline__ uint32_t packbf(__nv_bfloat16 a, __nv_bfloat16 b) {
    return (uint32_t)__bfloat16_as_ushort(a) | ((uint32_t)__bfloat16_as_ushort(b) << 16);
}
static __device__ __forceinline__ void split2(float x, float y, uint32_t& hi, uint32_t& lo) {
    __nv_bfloat16 hx = __float2bfloat16_rn(x);
    __nv_bfloat16 hy = __float2bfloat16_rn(y);
    hi = packbf(hx, hy);
    lo = packbf(__float2bfloat16_rn(x - __bfloat162float(hx)),
                __float2bfloat16_rn(y - __bfloat162float(hy)));
}
static __device__ __forceinline__ void cpa16(uint32_t dst, const void* src) {
    asm volatile("cp.async.cg.shared.global [%0], [%1], 16;" :: "r"(dst), "l"(src));
}
static __device__ __forceinline__ void cpa_commit() {
    asm volatile("cp.async.commit_group;" ::: "memory");
}

// ---------------- LayerNorm -> split bf16 ----------------
__global__ __launch_bounds__(256) void ln_kernel(const float* __restrict__ x,
                                                 const float* __restrict__ g,
                                                 __nv_bfloat16* __restrict__ oh,
                                                 __nv_bfloat16* __restrict__ ol) {
    int row = blockIdx.x;
    int tid = threadIdx.x;
    const float* xr = x + (size_t)row * DIMM;
    float4 v = *(const float4*)(xr + tid * 4);
    float s  = v.x + v.y + v.z + v.w;
    float ss = v.x * v.x + v.y * v.y + v.z * v.z + v.w * v.w;
#pragma unroll
    for (int off = 16; off; off >>= 1) {
        s  += __shfl_xor_sync(0xffffffffu, s, off);
        ss += __shfl_xor_sync(0xffffffffu, ss, off);
    }
    __shared__ float rs[8], rss[8];
    __shared__ float mu_s, rstd_s;
    int w = tid >> 5, lane = tid & 31;
    if (!lane) { rs[w] = s; rss[w] = ss; }
    __syncthreads();
    if (tid == 0) {
        float S = 0.f, SS = 0.f;
#pragma unroll
        for (int i = 0; i < 8; i++) { S += rs[i]; SS += rss[i]; }
        float mu  = S * (1.0f / DIMM);
        float var = SS * (1.0f / DIMM) - mu * mu;
        mu_s = mu;
        rstd_s = rsqrtf(var + 1e-5f);
    }
    __syncthreads();
    float mu = mu_s, r = rstd_s;
    float4 gv = *(const float4*)(g + tid * 4);
    float a0 = (v.x - mu) * r * gv.x;
    float a1 = (v.y - mu) * r * gv.y;
    float a2 = (v.z - mu) * r * gv.z;
    float a3 = (v.w - mu) * r * gv.w;
    uint2 hi, lo;
    split2(a0, a1, hi.x, lo.x);
    split2(a2, a3, hi.y, lo.y);
    size_t off = (size_t)row * DIMM + tid * 4;
    *(uint2*)(oh + off) = hi;
    *(uint2*)(ol + off) = lo;
}

// ---------------- transpose + split ----------------
__global__ __launch_bounds__(256) void transpose_split(const float* __restrict__ in,
                                                       __nv_bfloat16* __restrict__ oh,
                                                       __nv_bfloat16* __restrict__ ol,
                                                       int R, int C) {
    __shared__ float t[32][33];
    int bx = blockIdx.x * 32;
    int by = blockIdx.y * 32;
    int tx = threadIdx.x & 31, ty = threadIdx.x >> 5;
#pragma unroll
    for (int j = 0; j < 32; j += 8)
        t[ty + j][tx] = in[(size_t)(by + ty + j) * C + bx + tx];
    __syncthreads();
#pragma unroll
    for (int j = 0; j < 32; j += 8) {
        float v = t[tx][ty + j];
        __nv_bfloat16 hb = __float2bfloat16_rn(v);
        size_t off = (size_t)(bx + ty + j) * R + by + tx;
        oh[off] = hb;
        ol[off] = __float2bfloat16_rn(v - __bfloat162float(hb));
    }
}

// ---------------- double-buffered split-bf16 tensor-core GEMM ----------------
#define GP 80
#define STAGE_B (4 * 128 * GP)        // 40960
#define GEMM_SMEM (2 * STAGE_B)       // 81920

__global__ __launch_bounds__(256, 2) void gemm_split(const __nv_bfloat16* __restrict__ Ah,
                                                     const __nv_bfloat16* __restrict__ Al,
                                                     const __nv_bfloat16* __restrict__ Bh,
                                                     const __nv_bfloat16* __restrict__ Bl,
                                                     float* __restrict__ C,
                                                     int M, int N, int K) {
    extern __shared__ unsigned char smg[];
    uint32_t sb = s2u(smg);
    const uint32_t AH = 0, AL = 128 * GP, BHo = 2 * 128 * GP, BLo = 3 * 128 * GP;

    int tid = threadIdx.x;
    int lane = tid & 31;
    int w = tid >> 5;
    int wm = w & 1;
    int wn = w >> 1;
    int row0 = blockIdx.y * 128, col0 = blockIdx.x * 128;

    const __nv_bfloat16* srcs[4] = {Ah + (size_t)row0 * K, Al + (size_t)row0 * K,
                                    Bh + (size_t)col0 * K, Bl + (size_t)col0 * K};

    float acc[4][4][4];
#pragma unroll
    for (int i = 0; i < 4; i++)
#pragma unroll
        for (int j = 0; j < 4; j++)
#pragma unroll
            for (int q = 0; q < 4; q++) acc[i][j][q] = 0.f;

    // A x4: 16 rows, two 16B k-halves
    uint32_t aoff = (uint32_t)(lane & 15) * GP + (uint32_t)(lane >> 4) * 16;
    // B x4: lanes 0-7 rows+0 klo, 8-15 rows+0 khi, 16-23 rows+8 klo, 24-31 rows+8 khi
    uint32_t b4off = (uint32_t)(lane & 7) * GP + (uint32_t)((lane >> 3) & 1) * 16
                   + (uint32_t)(lane >> 4) * 8 * GP;

    const int nchunk = K >> 5;

#pragma unroll
    for (int it = 0; it < 8; it++) {
        int tile = it >> 1;
        int rem = (it & 1) * 256 + tid;
        int r = rem >> 2, f4 = rem & 3;
        cpa16(sb + tile * (128 * GP) + (uint32_t)r * GP + f4 * 16,
              srcs[tile] + (size_t)r * K + f4 * 8);
    }
    cpa_commit();

    for (int c = 0; c < nchunk; c++) {
        if (c + 1 < nchunk) {
            uint32_t st = sb + ((c + 1) & 1) * STAGE_B;
#pragma unroll
            for (int it = 0; it < 8; it++) {
                int tile = it >> 1;
                int rem = (it & 1) * 256 + tid;
                int r = rem >> 2, f4 = rem & 3;
                cpa16(st + tile * (128 * GP) + (uint32_t)r * GP + f4 * 16,
                      srcs[tile] + (size_t)r * K + (c + 1) * 32 + f4 * 8);
            }
            cpa_commit();
            asm volatile("cp.async.wait_group 1;" ::: "memory");
        } else {
            asm volatile("cp.async.wait_group 0;" ::: "memory");
        }
        __syncthreads();

        uint32_t st = sb + (c & 1) * STAGE_B;
#pragma unroll
        for (int ks = 0; ks < 2; ks++) {
            uint32_t bh[4][2], bl[4][2];
#pragma unroll
            for (int nip = 0; nip < 2; nip++) {
                uint32_t t4[4];
                uint32_t rowb = (uint32_t)(wn * 32 + nip * 16) * GP + ks * 32;
                ldm4(t4, st + BHo + rowb + b4off);
                bh[2 * nip][0] = t4[0]; bh[2 * nip][1] = t4[1];
                bh[2 * nip + 1][0] = t4[2]; bh[2 * nip + 1][1] = t4[3];
                ldm4(t4, st + BLo + rowb + b4off);
                bl[2 * nip][0] = t4[0]; bl[2 * nip][1] = t4[1];
                bl[2 * nip + 1][0] = t4[2]; bl[2 * nip + 1][1] = t4[3];
            }
#pragma unroll
            for (int mi = 0; mi < 4; mi++) {
                uint32_t rowa = (uint32_t)(wm * 64 + mi * 16) * GP + ks * 32;
                uint32_t ah[4], al[4];
                ldm4(ah, st + AH + rowa + aoff);
                ldm4(al, st + AL + rowa + aoff);
#pragma unroll
                for (int ni = 0; ni < 4; ni++) {
                    mma16816(acc[mi][ni], ah, bh[ni]);
                    mma16816(acc[mi][ni], ah, bl[ni]);
                    mma16816(acc[mi][ni], al, bh[ni]);
                }
            }
        }
        __syncthreads();
    }

    int g = lane >> 2, tg = lane & 3;
#pragma unroll
    for (int mi = 0; mi < 4; mi++) {
#pragma unroll
        for (int ni = 0; ni < 4; ni++) {
            int rg = row0 + wm * 64 + mi * 16 + g;
            int cg = col0 + wn * 32 + ni * 8 + tg * 2;
            float2 o0 = make_float2(acc[mi][ni][0], acc[mi][ni][1]);
            float2 o1 = make_float2(acc[mi][ni][2], acc[mi][ni][3]);
            *(float2*)(C + (size_t)rg * N + cg) = o0;
            *(float2*)(C + (size_t)(rg + 8) * N + cg) = o1;
        }
    }
}

// ---------------- RMS norm q,k + split all of qkv ----------------
__global__ __launch_bounds__(256) void rms_split(const float* __restrict__ qkv,
                                                 const float* __restrict__ qg,
                                                 const float* __restrict__ kg,
                                                 __nv_bfloat16* __restrict__ oh,
                                                 __nv_bfloat16* __restrict__ ol) {
    int w = (blockIdx.x * 256 + threadIdx.x) >> 5;
    int lane = threadIdx.x & 31;
    int qk  = w >> 17;
    int rem = w & 131071;
    int row = rem >> 4;
    int h   = rem & 15;
    size_t off = (size_t)row * 3072 + qk * 1024 + h * DH + lane * 2;
    float2 v = *(const float2*)(qkv + off);
    if (qk < 2) {
        float ss = v.x * v.x + v.y * v.y;
#pragma unroll
        for (int o = 16; o; o >>= 1) ss += __shfl_xor_sync(0xffffffffu, ss, o);
        float sc = 8.0f / fmaxf(sqrtf(ss), 1e-12f);
        const float* g = (qk ? kg : qg) + h * DH + lane * 2;
        v.x *= sc * g[0];
        v.y *= sc * g[1];
    }
    uint32_t hi, lo;
    split2(v.x, v.y, hi, lo);
    *(uint32_t*)(oh + off) = hi;
    *(uint32_t*)(ol + off) = lo;
}

// ---------------- flash attention on mma.sync bf16 (pre-split inputs) ----------------
#define FPIT 144
#define SQH 0
#define SQL (128 * FPIT)
#define SKH (2 * 128 * FPIT)
#define SKL (SKH + 64 * FPIT)
#define SVH (SKL + 64 * FPIT)
#define SVL (SVH + 64 * FPIT)
#define ATTN_SMEM (SVL + 64 * FPIT)   // 73728 B

__global__ __launch_bounds__(256, 2) void attn_mma(const __nv_bfloat16* __restrict__ qh,
                                                   const __nv_bfloat16* __restrict__ ql,
                                                   __nv_bfloat16* __restrict__ aoh,
                                                   __nv_bfloat16* __restrict__ aol) {
    extern __shared__ unsigned char smb[];
    uint32_t sb = s2u(smb);

    int tid = threadIdx.x;
    int lane = tid & 31;
    int w = tid >> 5;
    int bh = blockIdx.y;
    int b = bh >> 4, h = bh & 15;
    int i0 = blockIdx.x * 128;

    size_t base = (size_t)b * 1024 * 3072 + h * DH;
    const __nv_bfloat16* qbh = qh + base;
    const __nv_bfloat16* qbl = ql + base;
    const __nv_bfloat16* kbh = qh + base + 1024;
    const __nv_bfloat16* kbl = ql + base + 1024;
    const __nv_bfloat16* vbh = qh + base + 2048;
    const __nv_bfloat16* vbl = ql + base + 2048;

#pragma unroll
    for (int it = 0; it < 8; it++) {
        int idx = tid + it * 256;
        int r = idx >> 4;
        int f4 = idx & 15;
        size_t go = (size_t)(i0 + r) * 3072 + f4 * 4;
        uint32_t so = (uint32_t)r * FPIT + (uint32_t)f4 * 8;
        *(uint2*)(smb + SQH + so) = *(const uint2*)(qbh + go);
        *(uint2*)(smb + SQL + so) = *(const uint2*)(qbl + go);
    }

    float m0 = -1e30f, m1 = -1e30f, l0 = 0.f, l1 = 0.f;
    float O[8][4];
#pragma unroll
    for (int nd = 0; nd < 8; nd++)
#pragma unroll
        for (int q = 0; q < 4; q++) O[nd][q] = 0.f;

    uint32_t aoff = (uint32_t)(lane & 15) * FPIT + (uint32_t)(lane >> 4) * 16;
    // K x4 pairing: lanes 0-7 rows+0 klo, 8-15 khi, 16-23 rows+8 klo, 24-31 khi
    uint32_t k4off = (uint32_t)(lane & 7) * FPIT + (uint32_t)((lane >> 3) & 1) * 16
                   + (uint32_t)(lane >> 4) * 8 * FPIT;
    // V trans x4 pairing: lanes 0-15 rows 0-15 col nd, lanes 16-31 same rows col nd+1
    uint32_t v4off = (uint32_t)(lane & 15) * FPIT + (uint32_t)(lane >> 4) * 16;

    for (int jt = 0; jt < 16; jt++) {
        __syncthreads();
        int j0 = jt * 64;
#pragma unroll
        for (int it = 0; it < 8; it++) {
            int idx = tid + (it & 3) * 256;
            int r = idx >> 4;
            int f4 = idx & 15;
            size_t go = (size_t)(j0 + r) * 3072 + f4 * 4;
            uint32_t so = (uint32_t)r * FPIT + (uint32_t)f4 * 8;
            if (it < 4) {
                *(uint2*)(smb + SKH + so) = *(const uint2*)(kbh + go);
                *(uint2*)(smb + SKL + so) = *(const uint2*)(kbl + go);
            } else {
                *(uint2*)(smb + SVH + so) = *(const uint2*)(vbh + go);
                *(uint2*)(smb + SVL + so) = *(const uint2*)(vbl + go);
            }
        }
        __syncthreads();

        // ---- S = Q K^T ----
        float S[8][4];
#pragma unroll
        for (int jj = 0; jj < 8; jj++)
#pragma unroll
            for (int q = 0; q < 4; q++) S[jj][q] = 0.f;

#pragma unroll
        for (int ks = 0; ks < 4; ks++) {
            uint32_t qhv[4], qlv[4];
            uint32_t qa = (uint32_t)(w * 16) * FPIT + ks * 32 + aoff;
            ldm4(qhv, sb + SQH + qa);
            ldm4(qlv, sb + SQL + qa);
#pragma unroll
            for (int jp = 0; jp < 4; jp++) {
                uint32_t kh4[4], kl4[4];
                uint32_t ka = (uint32_t)(jp * 16) * FPIT + ks * 32 + k4off;
                ldm4(kh4, sb + SKH + ka);
                ldm4(kl4, sb + SKL + ka);
                mma16816(S[2 * jp], qhv, kh4);
                mma16816(S[2 * jp], qhv, kl4);
                mma16816(S[2 * jp], qlv, kh4);
                mma16816(S[2 * jp + 1], qhv, kh4 + 2);
                mma16816(S[2 * jp + 1], qhv, kl4 + 2);
                mma16816(S[2 * jp + 1], qlv, kh4 + 2);
            }
        }

        // ---- online softmax ----
        float mt0 = S[0][0], mt1 = S[0][2];
#pragma unroll
        for (int jj = 0; jj < 8; jj++) {
            mt0 = fmaxf(mt0, fmaxf(S[jj][0], S[jj][1]));
            mt1 = fmaxf(mt1, fmaxf(S[jj][2], S[jj][3]));
        }
        mt0 = fmaxf(mt0, __shfl_xor_sync(0xffffffffu, mt0, 1));
        mt0 = fmaxf(mt0, __shfl_xor_sync(0xffffffffu, mt0, 2));
        mt1 = fmaxf(mt1, __shfl_xor_sync(0xffffffffu, mt1, 1));
        mt1 = fmaxf(mt1, __shfl_xor_sync(0xffffffffu, mt1, 2));
        float mn0 = fmaxf(m0, mt0), mn1 = fmaxf(m1, mt1);
        float sc0 = __expf(m0 - mn0), sc1 = __expf(m1 - mn1);

        uint32_t Ph[8][2], Pl[8][2];
        float ls0 = 0.f, ls1 = 0.f;
#pragma unroll
        for (int jj = 0; jj < 8; jj++) {
            float p0 = __expf(S[jj][0] - mn0);
            float p1 = __expf(S[jj][1] - mn0);
            float p2 = __expf(S[jj][2] - mn1);
            float p3 = __expf(S[jj][3] - mn1);
            ls0 += p0 + p1;
            ls1 += p2 + p3;
            split2(p0, p1, Ph[jj][0], Pl[jj][0]);
            split2(p2, p3, Ph[jj][1], Pl[jj][1]);
        }
        ls0 += __shfl_xor_sync(0xffffffffu, ls0, 1);
        ls0 += __shfl_xor_sync(0xffffffffu, ls0, 2);
        ls1 += __shfl_xor_sync(0xffffffffu, ls1, 1);
        ls1 += __shfl_xor_sync(0xffffffffu, ls1, 2);
        l0 = l0 * sc0 + ls0;
        l1 = l1 * sc1 + ls1;
        m0 = mn0;
        m1 = mn1;

#pragma unroll
        for (int nd = 0; nd < 8; nd++) {
            O[nd][0] *= sc0; O[nd][1] *= sc0;
            O[nd][2] *= sc1; O[nd][3] *= sc1;
        }

        // ---- O += P V ----
#pragma unroll
        for (int kk = 0; kk < 4; kk++) {
            uint32_t ah[4] = {Ph[2 * kk][0], Ph[2 * kk][1], Ph[2 * kk + 1][0], Ph[2 * kk + 1][1]};
            uint32_t al[4] = {Pl[2 * kk][0], Pl[2 * kk][1], Pl[2 * kk + 1][0], Pl[2 * kk + 1][1]};
#pragma unroll
            for (int ndp = 0; ndp < 4; ndp++) {
                uint32_t vh4[4], vl4[4];
                uint32_t va = (uint32_t)(kk * 16) * FPIT + ndp * 32 + v4off;
                ldm4t(vh4, sb + SVH + va);
                ldm4t(vl4, sb + SVL + va);
                mma16816(O[2 * ndp], ah, vh4);
                mma16816(O[2 * ndp], ah, vl4);
                mma16816(O[2 * ndp], al, vh4);
                mma16816(O[2 * ndp + 1], ah, vh4 + 2);
                mma16816(O[2 * ndp + 1], ah, vl4 + 2);
                mma16816(O[2 * ndp + 1], al, vh4 + 2);
            }
        }
    }

    // ---- epilogue ----
    float inv0 = 1.0f / l0, inv1 = 1.0f / l1;
    int r0 = b * 1024 + i0 + w * 16 + (lane >> 2);
    int cg = h * DH + (lane & 3) * 2;
#pragma unroll
    for (int nd = 0; nd < 8; nd++) {
        uint32_t hi, lo;
        split2(O[nd][0] * inv0, O[nd][1] * inv0, hi, lo);
        *(uint32_t*)(aoh + (size_t)r0 * 1024 + cg + nd * 8) = hi;
        *(uint32_t*)(aol + (size_t)r0 * 1024 + cg + nd * 8) = lo;
        split2(O[nd][2] * inv1, O[nd][3] * inv1, hi, lo);
        *(uint32_t*)(aoh + (size_t)(r0 + 8) * 1024 + cg + nd * 8) = hi;
        *(uint32_t*)(aol + (size_t)(r0 + 8) * 1024 + cg + nd * 8) = lo;
    }
}

// ---------------- launch ----------------
extern "C" void kernel_launch(void* const* d_in, const int* in_sizes, int n_in,
                              void* d_out, int out_size) {
    const float* x     = (const float*)d_in[0];
    const float* ln_g  = (const float*)d_in[1];
    const float* qg    = (const float*)d_in[2];
    const float* kg    = (const float*)d_in[3];
    const float* wqkv  = (const float*)d_in[4];
    const float* wout  = (const float*)d_in[5];
    float* out = (float*)d_out;

    float* qkv;
    __nv_bfloat16 *xnh, *xnl, *qh, *ql, *aoh, *aol, *wth, *wtl, *w2h, *w2l;
    cudaGetSymbolAddress((void**)&qkv, g_qkv);
    cudaGetSymbolAddress((void**)&xnh, g_xnh);
    cudaGetSymbolAddress((void**)&xnl, g_xnl);
    cudaGetSymbolAddress((void**)&qh, g_qh);
    cudaGetSymbolAddress((void**)&ql, g_ql);
    cudaGetSymbolAddress((void**)&aoh, g_aoh);
    cudaGetSymbolAddress((void**)&aol, g_aol);
    cudaGetSymbolAddress((void**)&wth, g_wth);
    cudaGetSymbolAddress((void**)&wtl, g_wtl);
    cudaGetSymbolAddress((void**)&w2h, g_w2h);
    cudaGetSymbolAddress((void**)&w2l, g_w2l);

    cudaFuncSetAttribute((const void*)attn_mma,
                         cudaFuncAttributeMaxDynamicSharedMemorySize, ATTN_SMEM);
    cudaFuncSetAttribute((const void*)gemm_split,
                         cudaFuncAttributeMaxDynamicSharedMemorySize, GEMM_SMEM);

    ln_kernel<<<8192, 256>>>(x, ln_g, xnh, xnl);
    transpose_split<<<dim3(3072 / 32, 1024 / 32), 256>>>(wqkv, wth, wtl, 1024, 3072);
    transpose_split<<<dim3(1024 / 32, 1024 / 32), 256>>>(wout, w2h, w2l, 1024, 1024);
    gemm_split<<<dim3(3072 / 128, 8192 / 128), 256, GEMM_SMEM>>>(xnh, xnl, wth, wtl, qkv,
                                                                 8192, 3072, 1024);
    rms_split<<<49152, 256>>>(qkv, qg, kg, qh, ql);
    attn_mma<<<dim3(8, 128), 256, ATTN_SMEM>>>(qh, ql, aoh, aol);
    gemm_split<<<dim3(1024 / 128, 8192 / 128), 256, GEMM_SMEM>>>(aoh, aol, w2h, w2l, out,
                                                                 8192, 1024, 1024);
}